// round 10
// baseline (speedup 1.0000x reference)
#include <cuda_runtime.h>
#include <cuda_bf16.h>
#include <math.h>
#include <stdint.h>

// Problem constants
#define BB 16
#define TT 1024
#define CC 256
#define HH 4
#define KK 31
#define PADK 15
#define BT (BB * TT)          // 16384 tokens
#define C2 (2 * CC)           // 512
#define NSMALL (KK + HH * KK) // 155
#define NSP 160               // padded row stride for raw
#define NWW (HH * KK)         // 124
#define NSMPAD 256            // padded N rows for small weight

// -------------------- device scratch ---------------------------------------
__device__ float g_x[(size_t)BT * CC];
__device__ __nv_bfloat16 g_xhi[(size_t)BT * CC];
__device__ __nv_bfloat16 g_xlo[(size_t)BT * CC];
__device__ __nv_bfloat16 g_zhi[(size_t)BT * C2];
__device__ __nv_bfloat16 g_zlo[(size_t)BT * C2];
__device__ float g_raw[(size_t)BT * NSP];
__device__ float g_attn[(size_t)BT * NWW];
__device__ __nv_bfloat16 g_w1t_hi[(size_t)C2 * CC];
__device__ __nv_bfloat16 g_w1t_lo[(size_t)C2 * CC];
__device__ __nv_bfloat16 g_w2t_hi[(size_t)CC * C2];
__device__ __nv_bfloat16 g_w2t_lo[(size_t)CC * C2];
__device__ __nv_bfloat16 g_wst_hi[(size_t)NSMPAD * CC];
__device__ __nv_bfloat16 g_wst_lo[(size_t)NSMPAD * CC];
__device__ float g_bsmall[NSP];

static __device__ __forceinline__ void split2(float v, __nv_bfloat16& h, __nv_bfloat16& l) {
    h = __float2bfloat16(v);
    l = __float2bfloat16(v - __bfloat162float(h));
}

__device__ __forceinline__ void mma16816(float* c, uint32_t a0, uint32_t a1,
                                         uint32_t a2, uint32_t a3,
                                         uint32_t b0, uint32_t b1) {
    asm volatile(
        "mma.sync.aligned.m16n8k16.row.col.f32.bf16.bf16.f32 "
        "{%0,%1,%2,%3}, {%4,%5,%6,%7}, {%8,%9}, {%0,%1,%2,%3};"
        : "+f"(c[0]), "+f"(c[1]), "+f"(c[2]), "+f"(c[3])
        : "r"(a0), "r"(a1), "r"(a2), "r"(a3), "r"(b0), "r"(b1));
}

__device__ __forceinline__ uint32_t smem_u32(const void* p) {
    uint32_t a;
    asm("{ .reg .u64 t; cvta.to.shared.u64 t, %1; cvt.u32.u64 %0, t; }"
        : "=r"(a) : "l"(p));
    return a;
}
__device__ __forceinline__ void cpa16(uint32_t saddr, const void* g) {
    asm volatile("cp.async.cg.shared.global [%0], [%1], 16;" :: "r"(saddr), "l"(g));
}
#define CP_COMMIT() asm volatile("cp.async.commit_group;" ::: "memory")
#define CP_WAIT0()  asm volatile("cp.async.wait_group 0;" ::: "memory")

#define BMT 128
#define BNT 128
#define APAD 40   // bf16 elems per smem row
#define TILE_ELEMS (128 * APAD)

// ============ fused GEMM1 + GLU + split (512 threads) =======================
// CTA computes a-cols [bx*64, bx*64+64) and g-cols (+256). grid (4, BT/128).
// 16 warps: 4M x 4N, warp tile 32(M) x 16(N) for each of a/g.
#define G1_STAGE (4 * TILE_ELEMS)       // Ahi,Alo (128 rows) + 4 B tiles (64 rows)
#define G1_SMEM_BYTES (2 * G1_STAGE * 2)  // 81920

__global__ __launch_bounds__(512) void gemm1_glu(
    const float* __restrict__ Q,
    const __nv_bfloat16* __restrict__ Wh, const __nv_bfloat16* __restrict__ Wl,
    const float* __restrict__ b1,
    float* __restrict__ X, __nv_bfloat16* __restrict__ Xhi,
    __nv_bfloat16* __restrict__ Xlo)
{
    extern __shared__ __align__(16) __nv_bfloat16 sm[];
    const int tid = threadIdx.x;
    const int wid = tid >> 5;
    const int lane = tid & 31;
    const int m0 = blockIdx.y * BMT;
    const int na0 = blockIdx.x * 64;          // a-col base; g at +256
    const int wm = (wid & 3) * 32;
    const int wn = (wid >> 2) * 16;
    const int r8 = lane >> 2;
    const int cp = (lane & 3) * 2;
    const uint32_t smbase = smem_u32(sm);

    // B sources: Bah, Bal, Bgh, Bgl (64 rows each)
    const __nv_bfloat16* bsrc[4] = { Wh, Wl, Wh, Wl };
    const int brow[4] = { na0, na0, na0 + 256, na0 + 256 };

    // A loader: 1 chunk/thread/stage: row=tid>>2 (0..127), col=(tid&3)*8
    const int ar = tid >> 2, aq = (tid & 3) * 8;
    // B loader: 2 chunks/thread/stage over 1024 chunk ids
    int bt[2], br_[2], bq[2];
#pragma unroll
    for (int i = 0; i < 2; i++) {
        int c = tid + i * 512;
        bt[i] = c >> 8; int rem = c & 255;
        br_[i] = rem >> 2; bq[i] = (rem & 3) * 8;
    }

    float acc_a[2][2][4], acc_g[2][2][4];
#pragma unroll
    for (int i = 0; i < 2; i++)
#pragma unroll
        for (int j = 0; j < 2; j++)
#pragma unroll
            for (int q = 0; q < 4; q++) { acc_a[i][j][q] = 0.f; acc_g[i][j][q] = 0.f; }

    const int NK = CC / 32;  // 8
    float apre[8];

    // ---- prologue: stage 0
#pragma unroll
    for (int i = 0; i < 2; i++)
        cpa16(smbase + (uint32_t)(((256 + bt[i] * 64 + br_[i]) * APAD + bq[i]) * 2),
              bsrc[bt[i]] + (size_t)(brow[bt[i]] + br_[i]) * CC + bq[i]);
    CP_COMMIT();
    {
        *reinterpret_cast<float4*>(&apre[0]) = *reinterpret_cast<const float4*>(&Q[(size_t)(m0 + ar) * CC + aq]);
        *reinterpret_cast<float4*>(&apre[4]) = *reinterpret_cast<const float4*>(&Q[(size_t)(m0 + ar) * CC + aq + 4]);
        __nv_bfloat16 h8[8], l8[8];
#pragma unroll
        for (int e = 0; e < 8; e++) split2(apre[e], h8[e], l8[e]);
        *reinterpret_cast<uint4*>(&sm[(0 * 128 + ar) * APAD + aq]) = *reinterpret_cast<uint4*>(h8);
        *reinterpret_cast<uint4*>(&sm[(1 * 128 + ar) * APAD + aq]) = *reinterpret_cast<uint4*>(l8);
    }
    CP_WAIT0();
    __syncthreads();

    for (int kc = 0; kc < NK; kc++) {
        const int nxt = kc + 1;
        if (nxt < NK) {
            const int sb = (nxt & 1) * G1_STAGE;
            const int k0 = nxt << 5;
#pragma unroll
            for (int i = 0; i < 2; i++)
                cpa16(smbase + (uint32_t)((sb + (256 + bt[i] * 64 + br_[i]) * APAD + bq[i]) * 2),
                      bsrc[bt[i]] + (size_t)(brow[bt[i]] + br_[i]) * CC + k0 + bq[i]);
            CP_COMMIT();
            *reinterpret_cast<float4*>(&apre[0]) = *reinterpret_cast<const float4*>(&Q[(size_t)(m0 + ar) * CC + k0 + aq]);
            *reinterpret_cast<float4*>(&apre[4]) = *reinterpret_cast<const float4*>(&Q[(size_t)(m0 + ar) * CC + k0 + aq + 4]);
        }

        const __nv_bfloat16* Ah_ = sm + (kc & 1) * G1_STAGE;
        const __nv_bfloat16* Al_ = Ah_ + TILE_ELEMS;
        const __nv_bfloat16* Bb = Ah_ + 2 * TILE_ELEMS;
        const __nv_bfloat16* Bah = Bb;
        const __nv_bfloat16* Bal = Bb + 64 * APAD;
        const __nv_bfloat16* Bgh = Bb + 128 * APAD;
        const __nv_bfloat16* Bgl = Bb + 192 * APAD;
#pragma unroll
        for (int ks = 0; ks < 2; ks++) {
            const int kb = ks * 16;
            uint32_t afh[2][4], afl[2][4];
#pragma unroll
            for (int im = 0; im < 2; im++) {
                const int rb = wm + im * 16;
                afh[im][0] = *reinterpret_cast<const uint32_t*>(&Ah_[(rb + r8) * APAD + kb + cp]);
                afh[im][1] = *reinterpret_cast<const uint32_t*>(&Ah_[(rb + r8 + 8) * APAD + kb + cp]);
                afh[im][2] = *reinterpret_cast<const uint32_t*>(&Ah_[(rb + r8) * APAD + kb + cp + 8]);
                afh[im][3] = *reinterpret_cast<const uint32_t*>(&Ah_[(rb + r8 + 8) * APAD + kb + cp + 8]);
                afl[im][0] = *reinterpret_cast<const uint32_t*>(&Al_[(rb + r8) * APAD + kb + cp]);
                afl[im][1] = *reinterpret_cast<const uint32_t*>(&Al_[(rb + r8 + 8) * APAD + kb + cp]);
                afl[im][2] = *reinterpret_cast<const uint32_t*>(&Al_[(rb + r8) * APAD + kb + cp + 8]);
                afl[im][3] = *reinterpret_cast<const uint32_t*>(&Al_[(rb + r8 + 8) * APAD + kb + cp + 8]);
            }
#pragma unroll
            for (int jn = 0; jn < 2; jn++) {
                const int nb = wn + jn * 8;
                uint32_t bh0 = *reinterpret_cast<const uint32_t*>(&Bah[(nb + r8) * APAD + kb + cp]);
                uint32_t bh1 = *reinterpret_cast<const uint32_t*>(&Bah[(nb + r8) * APAD + kb + cp + 8]);
                uint32_t bl0 = *reinterpret_cast<const uint32_t*>(&Bal[(nb + r8) * APAD + kb + cp]);
                uint32_t bl1 = *reinterpret_cast<const uint32_t*>(&Bal[(nb + r8) * APAD + kb + cp + 8]);
#pragma unroll
                for (int im = 0; im < 2; im++) {
                    mma16816(acc_a[im][jn], afh[im][0], afh[im][1], afh[im][2], afh[im][3], bh0, bh1);
                    mma16816(acc_a[im][jn], afh[im][0], afh[im][1], afh[im][2], afh[im][3], bl0, bl1);
                    mma16816(acc_a[im][jn], afl[im][0], afl[im][1], afl[im][2], afl[im][3], bh0, bh1);
                }
                uint32_t gh0 = *reinterpret_cast<const uint32_t*>(&Bgh[(nb + r8) * APAD + kb + cp]);
                uint32_t gh1 = *reinterpret_cast<const uint32_t*>(&Bgh[(nb + r8) * APAD + kb + cp + 8]);
                uint32_t gl0 = *reinterpret_cast<const uint32_t*>(&Bgl[(nb + r8) * APAD + kb + cp]);
                uint32_t gl1 = *reinterpret_cast<const uint32_t*>(&Bgl[(nb + r8) * APAD + kb + cp + 8]);
#pragma unroll
                for (int im = 0; im < 2; im++) {
                    mma16816(acc_g[im][jn], afh[im][0], afh[im][1], afh[im][2], afh[im][3], gh0, gh1);
                    mma16816(acc_g[im][jn], afh[im][0], afh[im][1], afh[im][2], afh[im][3], gl0, gl1);
                    mma16816(acc_g[im][jn], afl[im][0], afl[im][1], afl[im][2], afl[im][3], gh0, gh1);
                }
            }
        }

        if (nxt < NK) {
            const int sb = (nxt & 1) * G1_STAGE;
            __nv_bfloat16 h8[8], l8[8];
#pragma unroll
            for (int e = 0; e < 8; e++) split2(apre[e], h8[e], l8[e]);
            *reinterpret_cast<uint4*>(&sm[sb + (0 * 128 + ar) * APAD + aq]) = *reinterpret_cast<uint4*>(h8);
            *reinterpret_cast<uint4*>(&sm[sb + (1 * 128 + ar) * APAD + aq]) = *reinterpret_cast<uint4*>(l8);
            CP_WAIT0();
            __syncthreads();
        }
    }

    // ---- epilogue: GLU + split
#pragma unroll
    for (int im = 0; im < 2; im++) {
#pragma unroll
        for (int jn = 0; jn < 2; jn++) {
            const int lc = wn + jn * 8 + cp;
            const int col = na0 + lc;
            const float ba0 = b1[col], ba1 = b1[col + 1];
            const float bg0 = b1[col + 256], bg1 = b1[col + 257];
            const int row0 = m0 + wm + im * 16 + r8;
#pragma unroll
            for (int half = 0; half < 2; half++) {
                const int row = row0 + half * 8;
                float a0 = acc_a[im][jn][half * 2 + 0] + ba0;
                float a1 = acc_a[im][jn][half * 2 + 1] + ba1;
                float gg0 = acc_g[im][jn][half * 2 + 0] + bg0;
                float gg1 = acc_g[im][jn][half * 2 + 1] + bg1;
                float x0 = a0 * (1.f / (1.f + expf(-gg0)));
                float x1 = a1 * (1.f / (1.f + expf(-gg1)));
                size_t o = (size_t)row * CC + col;
                *reinterpret_cast<float2*>(&X[o]) = make_float2(x0, x1);
                __nv_bfloat16 h0, l0, h1, l1;
                split2(x0, h0, l0); split2(x1, h1, l1);
                __nv_bfloat162 ph; ph.x = h0; ph.y = h1;
                __nv_bfloat162 pl; pl.x = l0; pl.y = l1;
                *reinterpret_cast<__nv_bfloat162*>(&Xhi[o]) = ph;
                *reinterpret_cast<__nv_bfloat162*>(&Xlo[o]) = pl;
            }
        }
    }
}

// ---------------- generic fused split-bf16 GEMM (512 threads) ---------------
#define STAGE_ELEMS (4 * TILE_ELEMS)
#define GSMEM_BYTES (2 * STAGE_ELEMS * 2)   // 81920

__global__ __launch_bounds__(512) void gemm_split_mma(
    const __nv_bfloat16* __restrict__ Ahi, const __nv_bfloat16* __restrict__ Alo,
    const __nv_bfloat16* __restrict__ Bhi, const __nv_bfloat16* __restrict__ Blo,
    const float* __restrict__ bias, float* __restrict__ Cm,
    int Kt, int ldc, int Nout)
{
    extern __shared__ __align__(16) __nv_bfloat16 sm[];
    const int tid = threadIdx.x;
    const int wid = tid >> 5;
    const int lane = tid & 31;
    const int m0 = blockIdx.y * BMT;
    const int n0 = blockIdx.x * BNT;
    const int wm = (wid & 3) * 32;
    const int wn = (wid >> 2) * 32;
    const int r8 = lane >> 2;
    const int cp = (lane & 3) * 2;
    const uint32_t smbase = smem_u32(sm);

    const __nv_bfloat16* srcs[4] = { Ahi, Alo, Bhi, Blo };
    const int bases[4] = { m0, m0, n0, n0 };

    // loader: 4 chunks/thread/stage over 2048 chunk ids
    int lt[4], lr[4], lq[4];
#pragma unroll
    for (int i = 0; i < 4; i++) {
        int c = tid + i * 512;
        lt[i] = c >> 9; int rem = c & 511;
        lr[i] = rem >> 2; lq[i] = (rem & 3) * 8;
    }

    float acc[2][4][4];
#pragma unroll
    for (int i = 0; i < 2; i++)
#pragma unroll
        for (int j = 0; j < 4; j++)
#pragma unroll
            for (int q = 0; q < 4; q++) acc[i][j][q] = 0.f;

    const int NK = Kt >> 5;

#pragma unroll
    for (int i = 0; i < 4; i++)
        cpa16(smbase + (uint32_t)(((lt[i] * 128 + lr[i]) * APAD + lq[i]) * 2),
              srcs[lt[i]] + (size_t)(bases[lt[i]] + lr[i]) * Kt + lq[i]);
    CP_COMMIT();
    CP_WAIT0();
    __syncthreads();

    for (int kc = 0; kc < NK; kc++) {
        if (kc + 1 < NK) {
            const int sb = ((kc + 1) & 1) * STAGE_ELEMS;
            const int k0 = (kc + 1) << 5;
#pragma unroll
            for (int i = 0; i < 4; i++)
                cpa16(smbase + (uint32_t)((sb + (lt[i] * 128 + lr[i]) * APAD + lq[i]) * 2),
                      srcs[lt[i]] + (size_t)(bases[lt[i]] + lr[i]) * Kt + k0 + lq[i]);
            CP_COMMIT();
        }
        const __nv_bfloat16* Ah_ = sm + (kc & 1) * STAGE_ELEMS;
        const __nv_bfloat16* Al_ = Ah_ + TILE_ELEMS;
        const __nv_bfloat16* Bh_ = Ah_ + 2 * TILE_ELEMS;
        const __nv_bfloat16* Bl_ = Ah_ + 3 * TILE_ELEMS;
#pragma unroll
        for (int ks = 0; ks < 2; ks++) {
            const int kb = ks * 16;
            uint32_t afh[2][4], afl[2][4];
#pragma unroll
            for (int im = 0; im < 2; im++) {
                const int rb = wm + im * 16;
                afh[im][0] = *reinterpret_cast<const uint32_t*>(&Ah_[(rb + r8) * APAD + kb + cp]);
                afh[im][1] = *reinterpret_cast<const uint32_t*>(&Ah_[(rb + r8 + 8) * APAD + kb + cp]);
                afh[im][2] = *reinterpret_cast<const uint32_t*>(&Ah_[(rb + r8) * APAD + kb + cp + 8]);
                afh[im][3] = *reinterpret_cast<const uint32_t*>(&Ah_[(rb + r8 + 8) * APAD + kb + cp + 8]);
                afl[im][0] = *reinterpret_cast<const uint32_t*>(&Al_[(rb + r8) * APAD + kb + cp]);
                afl[im][1] = *reinterpret_cast<const uint32_t*>(&Al_[(rb + r8 + 8) * APAD + kb + cp]);
                afl[im][2] = *reinterpret_cast<const uint32_t*>(&Al_[(rb + r8) * APAD + kb + cp + 8]);
                afl[im][3] = *reinterpret_cast<const uint32_t*>(&Al_[(rb + r8 + 8) * APAD + kb + cp + 8]);
            }
#pragma unroll
            for (int jn = 0; jn < 4; jn++) {
                const int nb = wn + jn * 8;
                uint32_t bh0 = *reinterpret_cast<const uint32_t*>(&Bh_[(nb + r8) * APAD + kb + cp]);
                uint32_t bh1 = *reinterpret_cast<const uint32_t*>(&Bh_[(nb + r8) * APAD + kb + cp + 8]);
                uint32_t bl0 = *reinterpret_cast<const uint32_t*>(&Bl_[(nb + r8) * APAD + kb + cp]);
                uint32_t bl1 = *reinterpret_cast<const uint32_t*>(&Bl_[(nb + r8) * APAD + kb + cp + 8]);
#pragma unroll
                for (int im = 0; im < 2; im++) {
                    mma16816(acc[im][jn], afh[im][0], afh[im][1], afh[im][2], afh[im][3], bh0, bh1);
                    mma16816(acc[im][jn], afh[im][0], afh[im][1], afh[im][2], afh[im][3], bl0, bl1);
                    mma16816(acc[im][jn], afl[im][0], afl[im][1], afl[im][2], afl[im][3], bh0, bh1);
                }
            }
        }
        if (kc + 1 < NK) {
            CP_WAIT0();
            __syncthreads();
        }
    }

#pragma unroll
    for (int im = 0; im < 2; im++) {
#pragma unroll
        for (int jn = 0; jn < 4; jn++) {
            const int col = n0 + wn + jn * 8 + cp;
            if (col < Nout) {
                const float bx = bias[col], by = bias[col + 1];
                const int row0 = m0 + wm + im * 16 + r8;
                float2 v0 = { acc[im][jn][0] + bx, acc[im][jn][1] + by };
                float2 v1 = { acc[im][jn][2] + bx, acc[im][jn][3] + by };
                *reinterpret_cast<float2*>(&Cm[(size_t)row0 * ldc + col]) = v0;
                *reinterpret_cast<float2*>(&Cm[(size_t)(row0 + 8) * ldc + col]) = v1;
            }
        }
    }
}

// -------------------- merged prep kernel ------------------------------------
#define S_W1 (C2 * CC)
#define S_W2 (CC * C2)
#define S_WS (NSMPAD * CC)
__global__ __launch_bounds__(256) void prep_all(
    const float* __restrict__ w1, const float* __restrict__ w2,
    const float* __restrict__ wf, const float* __restrict__ ww,
    const float* __restrict__ bf, const float* __restrict__ bw,
    __nv_bfloat16* __restrict__ w1h, __nv_bfloat16* __restrict__ w1l,
    __nv_bfloat16* __restrict__ w2h, __nv_bfloat16* __restrict__ w2l,
    __nv_bfloat16* __restrict__ wsh, __nv_bfloat16* __restrict__ wsl,
    float* __restrict__ bc)
{
    int i = blockIdx.x * 256 + threadIdx.x;
    if (i < S_W1) {
        int n = i / CC, k = i % CC;       // w1t[n][k] = w1[k][n], N=512
        split2(w1[(size_t)k * C2 + n], w1h[i], w1l[i]);
    } else if (i < S_W1 + S_W2) {
        int j = i - S_W1;
        int n = j / C2, k = j % C2;       // w2t[n][k] = w2[k][n], N=256
        split2(w2[(size_t)k * CC + n], w2h[j], w2l[j]);
    } else if (i < S_W1 + S_W2 + S_WS) {
        int j = i - S_W1 - S_W2;
        int n = j / CC, k = j % CC;
        float v = 0.f;
        if (n < KK) v = wf[k * KK + n];
        else if (n < NSMALL) v = ww[k * NWW + (n - KK)];
        split2(v, wsh[j], wsl[j]);
    } else if (i < S_W1 + S_W2 + S_WS + NSP) {
        int j = i - S_W1 - S_W2 - S_WS;
        float v = 0.f;
        if (j < KK) v = bf[j];
        else if (j < NSMALL) v = bw[j - KK];
        bc[j] = v;
    }
}

// ---------- per-token: channel conv xf + banded softmax (one warp/token) ----
__global__ __launch_bounds__(256) void post_small(
    const float* __restrict__ raw, const float* __restrict__ x,
    const int* __restrict__ mask, float* __restrict__ attn,
    __nv_bfloat16* __restrict__ zhi, __nv_bfloat16* __restrict__ zlo)
{
    __shared__ float xpad[8][CC + 2 * PADK];
    const int warp = threadIdx.x >> 5;
    const int lane = threadIdx.x & 31;
    const int t = blockIdx.x * 8 + warp;
    const int b = t >> 10;
    const int tt = t & 1023;

    float* xp = xpad[warp];
    for (int i = lane; i < CC + 2 * PADK; i += 32) {
        int c = i - PADK;
        xp[i] = (c >= 0 && c < CC) ? x[(size_t)t * CC + c] : 0.f;
    }
    __syncwarp();

    const float mk = (mask[b * TT + tt] != 0) ? 1.f : 0.f;
    float wv = (lane < KK) ? raw[(size_t)t * NSP + lane] : 0.f;
    float acc[8];
#pragma unroll
    for (int q = 0; q < 8; q++) acc[q] = 0.f;
    for (int j = 0; j < KK; j++) {
        float wj = __shfl_sync(0xffffffffu, wv, j);
#pragma unroll
        for (int q = 0; q < 8; q++) acc[q] = fmaf(wj, xp[lane + q * 32 + j], acc[q]);
    }
#pragma unroll
    for (int q = 0; q < 8; q++) {
        float v = acc[q] * mk;
        __nv_bfloat16 h_, l_;
        split2(v, h_, l_);
        size_t o = (size_t)t * C2 + CC + lane + q * 32;
        zhi[o] = h_; zlo[o] = l_;
    }

    const int s = tt + lane - PADK;
    const bool valid = (lane < KK) && (s >= 0) && (s < TT);
#pragma unroll
    for (int h = 0; h < HH; h++) {
        float v = valid ? raw[(size_t)t * NSP + KK + h * KK + lane] : -INFINITY;
        float mx = v;
#pragma unroll
        for (int o = 16; o; o >>= 1) mx = fmaxf(mx, __shfl_xor_sync(0xffffffffu, mx, o));
        float e = valid ? expf(v - mx) : 0.f;
        float sm = e;
#pragma unroll
        for (int o = 16; o; o >>= 1) sm += __shfl_xor_sync(0xffffffffu, sm, o);
        if (lane < KK) attn[(size_t)t * NWW + h * KK + lane] = e / sm;
    }
}

// ---------- banded attention apply ------------------------------------------
#define TCTILE 64
#define TCROWS (TCTILE + 2 * PADK) // 94
__global__ __launch_bounds__(256) void timeconv(
    const float* __restrict__ x, const float* __restrict__ attn,
    const int* __restrict__ mask,
    __nv_bfloat16* __restrict__ zhi, __nv_bfloat16* __restrict__ zlo)
{
    extern __shared__ float smemf[];
    float* xs = smemf;                       // TCROWS * CC
    float* ats = smemf + TCROWS * CC;        // TCTILE * NWW
    __shared__ float msk[TCTILE];

    const int b = blockIdx.x >> 4;
    const int tb = (blockIdx.x & 15) * TCTILE;
    const int tid = threadIdx.x;
    const int c = tid;

    for (int r = 0; r < TCROWS; r++) {
        int s = tb - PADK + r;
        xs[r * CC + c] = (s >= 0 && s < TT)
            ? x[((size_t)b * TT + s) * CC + c] : 0.f;
    }
    for (int i = tid; i < TCTILE * NWW; i += 256)
        ats[i] = attn[((size_t)b * TT + tb) * NWW + i];
    if (tid < TCTILE) msk[tid] = (mask[b * TT + tb + tid] != 0) ? 1.f : 0.f;
    __syncthreads();

    const int h = c >> 6;
    for (int tt = 0; tt < TCTILE; tt++) {
        const float* a = &ats[tt * NWW + h * KK];
        const float* xr = &xs[tt * CC + c];
        float acc = 0.f;
#pragma unroll
        for (int j = 0; j < KK; j++) acc = fmaf(a[j], xr[j * CC], acc);
        float v = acc * msk[tt];
        __nv_bfloat16 h_, l_;
        split2(v, h_, l_);
        size_t o = ((size_t)b * TT + tb + tt) * C2 + c;
        zhi[o] = h_; zlo[o] = l_;
    }
}

// ---------------------------------------------------------------------------
extern "C" void kernel_launch(void* const* d_in, const int* in_sizes, int n_in,
                              void* d_out, int out_size)
{
    const float* query = (const float*)d_in[0];
    const int* mask = (const int*)d_in[3];
    const float* w1 = (const float*)d_in[4];
    const float* b1 = (const float*)d_in[5];
    const float* w2 = (const float*)d_in[6];
    const float* b2 = (const float*)d_in[7];
    const float* ww = (const float*)d_in[8];
    const float* bw = (const float*)d_in[9];
    const float* wf = (const float*)d_in[10];
    const float* bf = (const float*)d_in[11];
    float* out = (float*)d_out;

    void* p;
    cudaGetSymbolAddress(&p, g_x);      float* dx = (float*)p;
    cudaGetSymbolAddress(&p, g_xhi);    __nv_bfloat16* dxhi = (__nv_bfloat16*)p;
    cudaGetSymbolAddress(&p, g_xlo);    __nv_bfloat16* dxlo = (__nv_bfloat16*)p;
    cudaGetSymbolAddress(&p, g_zhi);    __nv_bfloat16* dzhi = (__nv_bfloat16*)p;
    cudaGetSymbolAddress(&p, g_zlo);    __nv_bfloat16* dzlo = (__nv_bfloat16*)p;
    cudaGetSymbolAddress(&p, g_raw);    float* draw = (float*)p;
    cudaGetSymbolAddress(&p, g_attn);   float* dattn = (float*)p;
    cudaGetSymbolAddress(&p, g_w1t_hi); __nv_bfloat16* w1h = (__nv_bfloat16*)p;
    cudaGetSymbolAddress(&p, g_w1t_lo); __nv_bfloat16* w1l = (__nv_bfloat16*)p;
    cudaGetSymbolAddress(&p, g_w2t_hi); __nv_bfloat16* w2h = (__nv_bfloat16*)p;
    cudaGetSymbolAddress(&p, g_w2t_lo); __nv_bfloat16* w2l = (__nv_bfloat16*)p;
    cudaGetSymbolAddress(&p, g_wst_hi); __nv_bfloat16* wsh = (__nv_bfloat16*)p;
    cudaGetSymbolAddress(&p, g_wst_lo); __nv_bfloat16* wsl = (__nv_bfloat16*)p;
    cudaGetSymbolAddress(&p, g_bsmall); float* dbs = (float*)p;

    static bool attr_done = false;
    if (!attr_done) {
        cudaFuncSetAttribute(gemm1_glu,
                             cudaFuncAttributeMaxDynamicSharedMemorySize, G1_SMEM_BYTES);
        cudaFuncSetAttribute(gemm_split_mma,
                             cudaFuncAttributeMaxDynamicSharedMemorySize, GSMEM_BYTES);
        cudaFuncSetAttribute(timeconv, cudaFuncAttributeMaxDynamicSharedMemorySize,
                             (TCROWS * CC + TCTILE * NWW) * (int)sizeof(float));
        attr_done = true;
    }

    // prep: all weight splits in one launch
    prep_all<<<(S_W1 + S_W2 + S_WS + NSP + 255) / 256, 256>>>(
        w1, w2, wf, ww, bf, bw, w1h, w1l, w2h, w2l, wsh, wsl, dbs);

    // 1) x = GLU(query @ w1 + b1), fused
    gemm1_glu<<<dim3(4, BT / BMT), 512, G1_SMEM_BYTES>>>(
        query, w1h, w1l, b1, dx, dxhi, dxlo);
    // 2) raw = x @ [wf|ww] + [bf|bw]
    gemm_split_mma<<<dim3(NSMPAD / BNT, BT / BMT), 512, GSMEM_BYTES>>>(
        dxhi, dxlo, wsh, wsl, dbs, draw, CC, NSP, NSP);
    // 3) channel conv xf + banded softmax
    post_small<<<BT / 8, 256>>>(draw, dx, mask, dattn, dzhi, dzlo);
    // 4) banded attention apply
    timeconv<<<BB * (TT / TCTILE), 256,
               (TCROWS * CC + TCTILE * NWW) * sizeof(float)>>>(dx, dattn, mask, dzhi, dzlo);
    // 5) out = z @ w2 + b2
    gemm_split_mma<<<dim3(CC / BNT, BT / BMT), 512, GSMEM_BYTES>>>(
        dzhi, dzlo, w2h, w2l, b2, out, C2, CC, CC);
}

// round 11
// speedup vs baseline: 1.0797x; 1.0797x over previous
#include <cuda_runtime.h>
#include <cuda_bf16.h>
#include <math.h>
#include <stdint.h>

// Problem constants
#define BB 16
#define TT 1024
#define CC 256
#define HH 4
#define KK 31
#define PADK 15
#define BT (BB * TT)          // 16384 tokens
#define C2 (2 * CC)           // 512
#define NSMALL (KK + HH * KK) // 155
#define NSP 160               // padded row stride for raw
#define NWW (HH * KK)         // 124
#define NSMPAD 256            // padded N rows for small weight

// -------------------- device scratch ---------------------------------------
__device__ float g_x[(size_t)BT * CC];
__device__ __nv_bfloat16 g_xhi[(size_t)BT * CC];
__device__ __nv_bfloat16 g_xlo[(size_t)BT * CC];
__device__ __nv_bfloat16 g_zhi[(size_t)BT * C2];
__device__ __nv_bfloat16 g_zlo[(size_t)BT * C2];
__device__ float g_raw[(size_t)BT * NSP];
__device__ float g_attn[(size_t)BT * NWW];
__device__ __nv_bfloat16 g_w1t_hi[(size_t)C2 * CC];
__device__ __nv_bfloat16 g_w1t_lo[(size_t)C2 * CC];
__device__ __nv_bfloat16 g_w2t_hi[(size_t)CC * C2];
__device__ __nv_bfloat16 g_w2t_lo[(size_t)CC * C2];
__device__ __nv_bfloat16 g_wst_hi[(size_t)NSMPAD * CC];
__device__ __nv_bfloat16 g_wst_lo[(size_t)NSMPAD * CC];
__device__ float g_bsmall[NSP];

static __device__ __forceinline__ void split2(float v, __nv_bfloat16& h, __nv_bfloat16& l) {
    h = __float2bfloat16(v);
    l = __float2bfloat16(v - __bfloat162float(h));
}

__device__ __forceinline__ void mma16816(float* c, uint32_t a0, uint32_t a1,
                                         uint32_t a2, uint32_t a3,
                                         uint32_t b0, uint32_t b1) {
    asm volatile(
        "mma.sync.aligned.m16n8k16.row.col.f32.bf16.bf16.f32 "
        "{%0,%1,%2,%3}, {%4,%5,%6,%7}, {%8,%9}, {%0,%1,%2,%3};"
        : "+f"(c[0]), "+f"(c[1]), "+f"(c[2]), "+f"(c[3])
        : "r"(a0), "r"(a1), "r"(a2), "r"(a3), "r"(b0), "r"(b1));
}

__device__ __forceinline__ uint32_t smem_u32(const void* p) {
    uint32_t a;
    asm("{ .reg .u64 t; cvta.to.shared.u64 t, %1; cvt.u32.u64 %0, t; }"
        : "=r"(a) : "l"(p));
    return a;
}
__device__ __forceinline__ void cpa16(uint32_t saddr, const void* g) {
    asm volatile("cp.async.cg.shared.global [%0], [%1], 16;" :: "r"(saddr), "l"(g));
}
#define CP_COMMIT() asm volatile("cp.async.commit_group;" ::: "memory")
#define CP_WAIT0()  asm volatile("cp.async.wait_group 0;" ::: "memory")

#define BMT 128
#define BNT 128
#define APAD 40   // bf16 elems per smem row
#define TILE_ELEMS (128 * APAD)

// ============ fused GEMM1 + GLU + split (R9 config: 256 thr) ================
#define G1_STAGE (6 * TILE_ELEMS)
#define G1_SMEM_BYTES (2 * G1_STAGE * 2)   // 122880

__global__ __launch_bounds__(256) void gemm1_glu(
    const float* __restrict__ Q,
    const __nv_bfloat16* __restrict__ Wh, const __nv_bfloat16* __restrict__ Wl,
    const float* __restrict__ b1,
    float* __restrict__ X, __nv_bfloat16* __restrict__ Xhi,
    __nv_bfloat16* __restrict__ Xlo)
{
    extern __shared__ __align__(16) __nv_bfloat16 sm[];
    const int tid = threadIdx.x;
    const int wid = tid >> 5;
    const int lane = tid & 31;
    const int m0 = blockIdx.y * BMT;
    const int n0 = blockIdx.x * BNT;     // a-col base; g-cols at n0+256
    const int wm = (wid & 1) * 64;
    const int wn = (wid >> 1) * 32;
    const int r8 = lane >> 2;
    const int cp = (lane & 3) * 2;
    const uint32_t smbase = smem_u32(sm);

    const __nv_bfloat16* bsrc[4] = { Wh, Wl, Wh, Wl };
    const int brow[4] = { n0, n0, n0 + 256, n0 + 256 };

    const int c0 = tid, c1 = tid + 256;
    const int r0c = c0 >> 2, q0c = (c0 & 3) * 8;
    const int r1c = c1 >> 2, q1c = (c1 & 3) * 8;

    float acc_a[4][4][4], acc_g[4][4][4];
#pragma unroll
    for (int i = 0; i < 4; i++)
#pragma unroll
        for (int j = 0; j < 4; j++)
#pragma unroll
            for (int q = 0; q < 4; q++) { acc_a[i][j][q] = 0.f; acc_g[i][j][q] = 0.f; }

    const int NK = CC / 32;  // 8
    float apre[2][8];

#pragma unroll
    for (int t = 0; t < 4; t++) {
        cpa16(smbase + (uint32_t)(((t + 2) * 128 + r0c) * APAD + q0c) * 2,
              bsrc[t] + (size_t)(brow[t] + r0c) * CC + q0c);
        cpa16(smbase + (uint32_t)(((t + 2) * 128 + r1c) * APAD + q1c) * 2,
              bsrc[t] + (size_t)(brow[t] + r1c) * CC + q1c);
    }
    CP_COMMIT();
    {
        *reinterpret_cast<float4*>(&apre[0][0]) = *reinterpret_cast<const float4*>(&Q[(size_t)(m0 + r0c) * CC + q0c]);
        *reinterpret_cast<float4*>(&apre[0][4]) = *reinterpret_cast<const float4*>(&Q[(size_t)(m0 + r0c) * CC + q0c + 4]);
        *reinterpret_cast<float4*>(&apre[1][0]) = *reinterpret_cast<const float4*>(&Q[(size_t)(m0 + r1c) * CC + q1c]);
        *reinterpret_cast<float4*>(&apre[1][4]) = *reinterpret_cast<const float4*>(&Q[(size_t)(m0 + r1c) * CC + q1c + 4]);
        __nv_bfloat16 h8[8], l8[8];
#pragma unroll
        for (int e = 0; e < 8; e++) split2(apre[0][e], h8[e], l8[e]);
        *reinterpret_cast<uint4*>(&sm[(0 * 128 + r0c) * APAD + q0c]) = *reinterpret_cast<uint4*>(h8);
        *reinterpret_cast<uint4*>(&sm[(1 * 128 + r0c) * APAD + q0c]) = *reinterpret_cast<uint4*>(l8);
#pragma unroll
        for (int e = 0; e < 8; e++) split2(apre[1][e], h8[e], l8[e]);
        *reinterpret_cast<uint4*>(&sm[(0 * 128 + r1c) * APAD + q1c]) = *reinterpret_cast<uint4*>(h8);
        *reinterpret_cast<uint4*>(&sm[(1 * 128 + r1c) * APAD + q1c]) = *reinterpret_cast<uint4*>(l8);
    }
    CP_WAIT0();
    __syncthreads();

    for (int kc = 0; kc < NK; kc++) {
        const int nxt = kc + 1;
        if (nxt < NK) {
            const int sb = (nxt & 1) * G1_STAGE;
            const int k0 = nxt << 5;
#pragma unroll
            for (int t = 0; t < 4; t++) {
                cpa16(smbase + (uint32_t)(sb + ((t + 2) * 128 + r0c) * APAD + q0c) * 2,
                      bsrc[t] + (size_t)(brow[t] + r0c) * CC + k0 + q0c);
                cpa16(smbase + (uint32_t)(sb + ((t + 2) * 128 + r1c) * APAD + q1c) * 2,
                      bsrc[t] + (size_t)(brow[t] + r1c) * CC + k0 + q1c);
            }
            CP_COMMIT();
            *reinterpret_cast<float4*>(&apre[0][0]) = *reinterpret_cast<const float4*>(&Q[(size_t)(m0 + r0c) * CC + k0 + q0c]);
            *reinterpret_cast<float4*>(&apre[0][4]) = *reinterpret_cast<const float4*>(&Q[(size_t)(m0 + r0c) * CC + k0 + q0c + 4]);
            *reinterpret_cast<float4*>(&apre[1][0]) = *reinterpret_cast<const float4*>(&Q[(size_t)(m0 + r1c) * CC + k0 + q1c]);
            *reinterpret_cast<float4*>(&apre[1][4]) = *reinterpret_cast<const float4*>(&Q[(size_t)(m0 + r1c) * CC + k0 + q1c + 4]);
        }

        const __nv_bfloat16* Ah_ = sm + (kc & 1) * G1_STAGE;
        const __nv_bfloat16* Al_ = Ah_ + TILE_ELEMS;
        const __nv_bfloat16* Bah = Ah_ + 2 * TILE_ELEMS;
        const __nv_bfloat16* Bal = Ah_ + 3 * TILE_ELEMS;
        const __nv_bfloat16* Bgh = Ah_ + 4 * TILE_ELEMS;
        const __nv_bfloat16* Bgl = Ah_ + 5 * TILE_ELEMS;
#pragma unroll
        for (int ks = 0; ks < 2; ks++) {
            const int kb = ks * 16;
            uint32_t afh[4][4], afl[4][4];
#pragma unroll
            for (int im = 0; im < 4; im++) {
                const int rb = wm + im * 16;
                afh[im][0] = *reinterpret_cast<const uint32_t*>(&Ah_[(rb + r8) * APAD + kb + cp]);
                afh[im][1] = *reinterpret_cast<const uint32_t*>(&Ah_[(rb + r8 + 8) * APAD + kb + cp]);
                afh[im][2] = *reinterpret_cast<const uint32_t*>(&Ah_[(rb + r8) * APAD + kb + cp + 8]);
                afh[im][3] = *reinterpret_cast<const uint32_t*>(&Ah_[(rb + r8 + 8) * APAD + kb + cp + 8]);
                afl[im][0] = *reinterpret_cast<const uint32_t*>(&Al_[(rb + r8) * APAD + kb + cp]);
                afl[im][1] = *reinterpret_cast<const uint32_t*>(&Al_[(rb + r8 + 8) * APAD + kb + cp]);
                afl[im][2] = *reinterpret_cast<const uint32_t*>(&Al_[(rb + r8) * APAD + kb + cp + 8]);
                afl[im][3] = *reinterpret_cast<const uint32_t*>(&Al_[(rb + r8 + 8) * APAD + kb + cp + 8]);
            }
            {
                uint32_t bh[4][2], bl[4][2];
#pragma unroll
                for (int jn = 0; jn < 4; jn++) {
                    const int nb = wn + jn * 8;
                    bh[jn][0] = *reinterpret_cast<const uint32_t*>(&Bah[(nb + r8) * APAD + kb + cp]);
                    bh[jn][1] = *reinterpret_cast<const uint32_t*>(&Bah[(nb + r8) * APAD + kb + cp + 8]);
                    bl[jn][0] = *reinterpret_cast<const uint32_t*>(&Bal[(nb + r8) * APAD + kb + cp]);
                    bl[jn][1] = *reinterpret_cast<const uint32_t*>(&Bal[(nb + r8) * APAD + kb + cp + 8]);
                }
#pragma unroll
                for (int im = 0; im < 4; im++)
#pragma unroll
                    for (int jn = 0; jn < 4; jn++) {
                        mma16816(acc_a[im][jn], afh[im][0], afh[im][1], afh[im][2], afh[im][3], bh[jn][0], bh[jn][1]);
                        mma16816(acc_a[im][jn], afh[im][0], afh[im][1], afh[im][2], afh[im][3], bl[jn][0], bl[jn][1]);
                        mma16816(acc_a[im][jn], afl[im][0], afl[im][1], afl[im][2], afl[im][3], bh[jn][0], bh[jn][1]);
                    }
            }
            {
                uint32_t bh[4][2], bl[4][2];
#pragma unroll
                for (int jn = 0; jn < 4; jn++) {
                    const int nb = wn + jn * 8;
                    bh[jn][0] = *reinterpret_cast<const uint32_t*>(&Bgh[(nb + r8) * APAD + kb + cp]);
                    bh[jn][1] = *reinterpret_cast<const uint32_t*>(&Bgh[(nb + r8) * APAD + kb + cp + 8]);
                    bl[jn][0] = *reinterpret_cast<const uint32_t*>(&Bgl[(nb + r8) * APAD + kb + cp]);
                    bl[jn][1] = *reinterpret_cast<const uint32_t*>(&Bgl[(nb + r8) * APAD + kb + cp + 8]);
                }
#pragma unroll
                for (int im = 0; im < 4; im++)
#pragma unroll
                    for (int jn = 0; jn < 4; jn++) {
                        mma16816(acc_g[im][jn], afh[im][0], afh[im][1], afh[im][2], afh[im][3], bh[jn][0], bh[jn][1]);
                        mma16816(acc_g[im][jn], afh[im][0], afh[im][1], afh[im][2], afh[im][3], bl[jn][0], bl[jn][1]);
                        mma16816(acc_g[im][jn], afl[im][0], afl[im][1], afl[im][2], afl[im][3], bh[jn][0], bh[jn][1]);
                    }
            }
        }

        if (nxt < NK) {
            const int sb = (nxt & 1) * G1_STAGE;
            __nv_bfloat16 h8[8], l8[8];
#pragma unroll
            for (int e = 0; e < 8; e++) split2(apre[0][e], h8[e], l8[e]);
            *reinterpret_cast<uint4*>(&sm[sb + (0 * 128 + r0c) * APAD + q0c]) = *reinterpret_cast<uint4*>(h8);
            *reinterpret_cast<uint4*>(&sm[sb + (1 * 128 + r0c) * APAD + q0c]) = *reinterpret_cast<uint4*>(l8);
#pragma unroll
            for (int e = 0; e < 8; e++) split2(apre[1][e], h8[e], l8[e]);
            *reinterpret_cast<uint4*>(&sm[sb + (0 * 128 + r1c) * APAD + q1c]) = *reinterpret_cast<uint4*>(h8);
            *reinterpret_cast<uint4*>(&sm[sb + (1 * 128 + r1c) * APAD + q1c]) = *reinterpret_cast<uint4*>(l8);
            CP_WAIT0();
            __syncthreads();
        }
    }

#pragma unroll
    for (int im = 0; im < 4; im++) {
#pragma unroll
        for (int jn = 0; jn < 4; jn++) {
            const int lc = wn + jn * 8 + cp;
            const int col = n0 + lc;
            const float ba0 = b1[col], ba1 = b1[col + 1];
            const float bg0 = b1[col + 256], bg1 = b1[col + 257];
            const int row0 = m0 + wm + im * 16 + r8;
#pragma unroll
            for (int half = 0; half < 2; half++) {
                const int row = row0 + half * 8;
                float a0 = acc_a[im][jn][half * 2 + 0] + ba0;
                float a1 = acc_a[im][jn][half * 2 + 1] + ba1;
                float gg0 = acc_g[im][jn][half * 2 + 0] + bg0;
                float gg1 = acc_g[im][jn][half * 2 + 1] + bg1;
                float x0 = a0 * (1.f / (1.f + expf(-gg0)));
                float x1 = a1 * (1.f / (1.f + expf(-gg1)));
                size_t o = (size_t)row * CC + col;
                *reinterpret_cast<float2*>(&X[o]) = make_float2(x0, x1);
                __nv_bfloat16 h0, l0, h1, l1;
                split2(x0, h0, l0); split2(x1, h1, l1);
                __nv_bfloat162 ph; ph.x = h0; ph.y = h1;
                __nv_bfloat162 pl; pl.x = l0; pl.y = l1;
                *reinterpret_cast<__nv_bfloat162*>(&Xhi[o]) = ph;
                *reinterpret_cast<__nv_bfloat162*>(&Xlo[o]) = pl;
            }
        }
    }
}

// ---------------- generic fused split-bf16 GEMM (R9 config: 256 thr) --------
#define STAGE_ELEMS (4 * TILE_ELEMS)
#define GSMEM_BYTES (2 * STAGE_ELEMS * 2)   // 81920

__global__ __launch_bounds__(256) void gemm_split_mma(
    const __nv_bfloat16* __restrict__ Ahi, const __nv_bfloat16* __restrict__ Alo,
    const __nv_bfloat16* __restrict__ Bhi, const __nv_bfloat16* __restrict__ Blo,
    const float* __restrict__ bias, float* __restrict__ Cm,
    int Kt, int ldc, int Nout)
{
    extern __shared__ __align__(16) __nv_bfloat16 sm[];
    const int tid = threadIdx.x;
    const int wid = tid >> 5;
    const int lane = tid & 31;
    const int m0 = blockIdx.y * BMT;
    const int n0 = blockIdx.x * BNT;
    const int wm = (wid & 1) * 64;
    const int wn = (wid >> 1) * 32;
    const int r8 = lane >> 2;
    const int cp = (lane & 3) * 2;

    const __nv_bfloat16* srcs[4] = { Ahi, Alo, Bhi, Blo };
    const int bases[4] = { m0, m0, n0, n0 };

    const int c0 = tid, c1 = tid + 256;
    const int lr0 = c0 >> 2, lc0 = (c0 & 3) * 8;
    const int lr1 = c1 >> 2, lc1 = (c1 & 3) * 8;
    const uint32_t smbase = smem_u32(sm);

    float acc[4][4][4];
#pragma unroll
    for (int i = 0; i < 4; i++)
#pragma unroll
        for (int j = 0; j < 4; j++)
#pragma unroll
            for (int q = 0; q < 4; q++) acc[i][j][q] = 0.f;

    const int NK = Kt >> 5;

#pragma unroll
    for (int t = 0; t < 4; t++) {
        const __nv_bfloat16* sp = srcs[t];
        cpa16(smbase + (uint32_t)((t * 128 + lr0) * APAD + lc0) * 2,
              sp + (size_t)(bases[t] + lr0) * Kt + lc0);
        cpa16(smbase + (uint32_t)((t * 128 + lr1) * APAD + lc1) * 2,
              sp + (size_t)(bases[t] + lr1) * Kt + lc1);
    }
    CP_COMMIT();
    CP_WAIT0();
    __syncthreads();

    for (int kc = 0; kc < NK; kc++) {
        if (kc + 1 < NK) {
            const int sb = ((kc + 1) & 1) * STAGE_ELEMS;
            const int k0 = (kc + 1) << 5;
#pragma unroll
            for (int t = 0; t < 4; t++) {
                const __nv_bfloat16* sp = srcs[t];
                cpa16(smbase + (uint32_t)(sb + (t * 128 + lr0) * APAD + lc0) * 2,
                      sp + (size_t)(bases[t] + lr0) * Kt + k0 + lc0);
                cpa16(smbase + (uint32_t)(sb + (t * 128 + lr1) * APAD + lc1) * 2,
                      sp + (size_t)(bases[t] + lr1) * Kt + k0 + lc1);
            }
            CP_COMMIT();
        }
        const __nv_bfloat16* Ah_ = sm + (kc & 1) * STAGE_ELEMS;
        const __nv_bfloat16* Al_ = Ah_ + TILE_ELEMS;
        const __nv_bfloat16* Bh_ = Ah_ + 2 * TILE_ELEMS;
        const __nv_bfloat16* Bl_ = Ah_ + 3 * TILE_ELEMS;
#pragma unroll
        for (int ks = 0; ks < 2; ks++) {
            const int kb = ks * 16;
            uint32_t afh[4][4], afl[4][4];
#pragma unroll
            for (int im = 0; im < 4; im++) {
                const int rb = wm + im * 16;
                afh[im][0] = *reinterpret_cast<const uint32_t*>(&Ah_[(rb + r8) * APAD + kb + cp]);
                afh[im][1] = *reinterpret_cast<const uint32_t*>(&Ah_[(rb + r8 + 8) * APAD + kb + cp]);
                afh[im][2] = *reinterpret_cast<const uint32_t*>(&Ah_[(rb + r8) * APAD + kb + cp + 8]);
                afh[im][3] = *reinterpret_cast<const uint32_t*>(&Ah_[(rb + r8 + 8) * APAD + kb + cp + 8]);
            }
            uint32_t bfh[4][2], bfl[4][2];
#pragma unroll
            for (int jn = 0; jn < 4; jn++) {
                const int nb = wn + jn * 8;
                bfh[jn][0] = *reinterpret_cast<const uint32_t*>(&Bh_[(nb + r8) * APAD + kb + cp]);
                bfh[jn][1] = *reinterpret_cast<const uint32_t*>(&Bh_[(nb + r8) * APAD + kb + cp + 8]);
                bfl[jn][0] = *reinterpret_cast<const uint32_t*>(&Bl_[(nb + r8) * APAD + kb + cp]);
                bfl[jn][1] = *reinterpret_cast<const uint32_t*>(&Bl_[(nb + r8) * APAD + kb + cp + 8]);
            }
#pragma unroll
            for (int im = 0; im < 4; im++)
#pragma unroll
                for (int jn = 0; jn < 4; jn++) {
                    mma16816(acc[im][jn], afh[im][0], afh[im][1], afh[im][2], afh[im][3], bfh[jn][0], bfh[jn][1]);
                    mma16816(acc[im][jn], afh[im][0], afh[im][1], afh[im][2], afh[im][3], bfl[jn][0], bfl[jn][1]);
                }
#pragma unroll
            for (int im = 0; im < 4; im++) {
                const int rb = wm + im * 16;
                afl[im][0] = *reinterpret_cast<const uint32_t*>(&Al_[(rb + r8) * APAD + kb + cp]);
                afl[im][1] = *reinterpret_cast<const uint32_t*>(&Al_[(rb + r8 + 8) * APAD + kb + cp]);
                afl[im][2] = *reinterpret_cast<const uint32_t*>(&Al_[(rb + r8) * APAD + kb + cp + 8]);
                afl[im][3] = *reinterpret_cast<const uint32_t*>(&Al_[(rb + r8 + 8) * APAD + kb + cp + 8]);
            }
#pragma unroll
            for (int im = 0; im < 4; im++)
#pragma unroll
                for (int jn = 0; jn < 4; jn++)
                    mma16816(acc[im][jn], afl[im][0], afl[im][1], afl[im][2], afl[im][3], bfh[jn][0], bfh[jn][1]);
        }
        if (kc + 1 < NK) {
            CP_WAIT0();
            __syncthreads();
        }
    }

#pragma unroll
    for (int im = 0; im < 4; im++) {
#pragma unroll
        for (int jn = 0; jn < 4; jn++) {
            const int col = n0 + wn + jn * 8 + cp;
            if (col < Nout) {
                const float bx = bias[col], by = bias[col + 1];
                const int row0 = m0 + wm + im * 16 + r8;
                float2 v0 = { acc[im][jn][0] + bx, acc[im][jn][1] + by };
                float2 v1 = { acc[im][jn][2] + bx, acc[im][jn][3] + by };
                *reinterpret_cast<float2*>(&Cm[(size_t)row0 * ldc + col]) = v0;
                *reinterpret_cast<float2*>(&Cm[(size_t)(row0 + 8) * ldc + col]) = v1;
            }
        }
    }
}

// -------------------- merged prep kernel ------------------------------------
#define S_W1 (C2 * CC)
#define S_W2 (CC * C2)
#define S_WS (NSMPAD * CC)
__global__ __launch_bounds__(256) void prep_all(
    const float* __restrict__ w1, const float* __restrict__ w2,
    const float* __restrict__ wf, const float* __restrict__ ww,
    const float* __restrict__ bf, const float* __restrict__ bw,
    __nv_bfloat16* __restrict__ w1h, __nv_bfloat16* __restrict__ w1l,
    __nv_bfloat16* __restrict__ w2h, __nv_bfloat16* __restrict__ w2l,
    __nv_bfloat16* __restrict__ wsh, __nv_bfloat16* __restrict__ wsl,
    float* __restrict__ bc)
{
    int i = blockIdx.x * 256 + threadIdx.x;
    if (i < S_W1) {
        int n = i / CC, k = i % CC;
        split2(w1[(size_t)k * C2 + n], w1h[i], w1l[i]);
    } else if (i < S_W1 + S_W2) {
        int j = i - S_W1;
        int n = j / C2, k = j % C2;
        split2(w2[(size_t)k * CC + n], w2h[j], w2l[j]);
    } else if (i < S_W1 + S_W2 + S_WS) {
        int j = i - S_W1 - S_W2;
        int n = j / CC, k = j % CC;
        float v = 0.f;
        if (n < KK) v = wf[k * KK + n];
        else if (n < NSMALL) v = ww[k * NWW + (n - KK)];
        split2(v, wsh[j], wsl[j]);
    } else if (i < S_W1 + S_W2 + S_WS + NSP) {
        int j = i - S_W1 - S_W2 - S_WS;
        float v = 0.f;
        if (j < KK) v = bf[j];
        else if (j < NSMALL) v = bw[j - KK];
        bc[j] = v;
    }
}

// ---------- per-token conv + softmax: register-window version ---------------
__global__ __launch_bounds__(256) void post_small(
    const float* __restrict__ raw, const float* __restrict__ x,
    const int* __restrict__ mask, float* __restrict__ attn,
    __nv_bfloat16* __restrict__ zhi, __nv_bfloat16* __restrict__ zlo)
{
    __shared__ float xpad[8][288];   // 286 used (CC + 2*PADK), padded for f4
    const int warp = threadIdx.x >> 5;
    const int lane = threadIdx.x & 31;
    const int t = blockIdx.x * 8 + warp;
    const int b = t >> 10;
    const int tt = t & 1023;

    float* xp = xpad[warp];
#pragma unroll
    for (int i = lane; i < 288; i += 32) {
        int c = i - PADK;
        xp[i] = (c >= 0 && c < CC) ? x[(size_t)t * CC + c] : 0.f;
    }
    __syncwarp();

    const float mk = (mask[b * TT + tt] != 0) ? 1.f : 0.f;
    float wv = (lane < KK) ? raw[(size_t)t * NSP + lane] : 0.f;

    // register window: xp[lane*8 .. lane*8+39]
    float win[40];
#pragma unroll
    for (int i = 0; i < 10; i++)
        *reinterpret_cast<float4*>(&win[i * 4]) =
            *reinterpret_cast<const float4*>(&xp[lane * 8 + i * 4]);

    float acc[8];
#pragma unroll
    for (int d = 0; d < 8; d++) acc[d] = 0.f;
#pragma unroll
    for (int j = 0; j < KK; j++) {
        float wj = __shfl_sync(0xffffffffu, wv, j);
#pragma unroll
        for (int d = 0; d < 8; d++) acc[d] = fmaf(wj, win[d + j], acc[d]);
    }
    {
        __nv_bfloat16 h8[8], l8[8];
#pragma unroll
        for (int d = 0; d < 8; d++) split2(acc[d] * mk, h8[d], l8[d]);
        size_t o = (size_t)t * C2 + CC + lane * 8;
        *reinterpret_cast<uint4*>(&zhi[o]) = *reinterpret_cast<uint4*>(h8);
        *reinterpret_cast<uint4*>(&zlo[o]) = *reinterpret_cast<uint4*>(l8);
    }

    const int s = tt + lane - PADK;
    const bool valid = (lane < KK) && (s >= 0) && (s < TT);
#pragma unroll
    for (int h = 0; h < HH; h++) {
        float v = valid ? raw[(size_t)t * NSP + KK + h * KK + lane] : -INFINITY;
        float mx = v;
#pragma unroll
        for (int o = 16; o; o >>= 1) mx = fmaxf(mx, __shfl_xor_sync(0xffffffffu, mx, o));
        float e = valid ? expf(v - mx) : 0.f;
        float sm = e;
#pragma unroll
        for (int o = 16; o; o >>= 1) sm += __shfl_xor_sync(0xffffffffu, sm, o);
        if (lane < KK) attn[(size_t)t * NWW + h * KK + lane] = e / sm;
    }
}

// ---------- banded attention apply: warp-per-token, shuffle attn ------------
#define TCT 32
#define TCR (TCT + 2 * PADK)   // 62
#define TC_SMEM ((TCR * CC + TCT * NWW) * (int)sizeof(float))
__global__ __launch_bounds__(256) void timeconv(
    const float* __restrict__ x, const float* __restrict__ attn,
    const int* __restrict__ mask,
    __nv_bfloat16* __restrict__ zhi, __nv_bfloat16* __restrict__ zlo)
{
    extern __shared__ float smemf[];
    float* xs = smemf;                       // TCR * CC
    float* ats = smemf + TCR * CC;           // TCT * NWW
    __shared__ float msk[TCT];

    const int b = blockIdx.x >> 5;           // 32 tiles per batch
    const int tb = (blockIdx.x & 31) * TCT;
    const int tid = threadIdx.x;
    const int warp = tid >> 5;
    const int lane = tid & 31;

    for (int r = 0; r < TCR; r++) {
        int s = tb - PADK + r;
        xs[r * CC + tid] = (s >= 0 && s < TT)
            ? x[((size_t)b * TT + s) * CC + tid] : 0.f;
    }
    for (int i = tid; i < TCT * NWW; i += 256)
        ats[i] = attn[((size_t)b * TT + tb) * NWW + i];
    if (tid < TCT) msk[tid] = (mask[b * TT + tb + tid] != 0) ? 1.f : 0.f;
    __syncthreads();

#pragma unroll
    for (int it = 0; it < 4; it++) {
        const int tt = warp * 4 + it;
        // per-head attn in lane registers
        float wv0 = (lane < KK) ? ats[tt * NWW + 0 * KK + lane] : 0.f;
        float wv1 = (lane < KK) ? ats[tt * NWW + 1 * KK + lane] : 0.f;
        float wv2 = (lane < KK) ? ats[tt * NWW + 2 * KK + lane] : 0.f;
        float wv3 = (lane < KK) ? ats[tt * NWW + 3 * KK + lane] : 0.f;
        float acc[8];
#pragma unroll
        for (int g = 0; g < 8; g++) acc[g] = 0.f;
#pragma unroll
        for (int j = 0; j < KK; j++) {
            float w0 = __shfl_sync(0xffffffffu, wv0, j);
            float w1 = __shfl_sync(0xffffffffu, wv1, j);
            float w2 = __shfl_sync(0xffffffffu, wv2, j);
            float w3 = __shfl_sync(0xffffffffu, wv3, j);
            const float* xr = &xs[(tt + j) * CC + lane];
            acc[0] = fmaf(w0, xr[0 * 32], acc[0]);
            acc[1] = fmaf(w0, xr[1 * 32], acc[1]);
            acc[2] = fmaf(w1, xr[2 * 32], acc[2]);
            acc[3] = fmaf(w1, xr[3 * 32], acc[3]);
            acc[4] = fmaf(w2, xr[4 * 32], acc[4]);
            acc[5] = fmaf(w2, xr[5 * 32], acc[5]);
            acc[6] = fmaf(w3, xr[6 * 32], acc[6]);
            acc[7] = fmaf(w3, xr[7 * 32], acc[7]);
        }
        const float mv = msk[tt];
        const size_t obase = ((size_t)b * TT + tb + tt) * C2 + lane;
#pragma unroll
        for (int g = 0; g < 8; g++) {
            __nv_bfloat16 h_, l_;
            split2(acc[g] * mv, h_, l_);
            zhi[obase + g * 32] = h_;
            zlo[obase + g * 32] = l_;
        }
    }
}

// ---------------------------------------------------------------------------
extern "C" void kernel_launch(void* const* d_in, const int* in_sizes, int n_in,
                              void* d_out, int out_size)
{
    const float* query = (const float*)d_in[0];
    const int* mask = (const int*)d_in[3];
    const float* w1 = (const float*)d_in[4];
    const float* b1 = (const float*)d_in[5];
    const float* w2 = (const float*)d_in[6];
    const float* b2 = (const float*)d_in[7];
    const float* ww = (const float*)d_in[8];
    const float* bw = (const float*)d_in[9];
    const float* wf = (const float*)d_in[10];
    const float* bf = (const float*)d_in[11];
    float* out = (float*)d_out;

    void* p;
    cudaGetSymbolAddress(&p, g_x);      float* dx = (float*)p;
    cudaGetSymbolAddress(&p, g_xhi);    __nv_bfloat16* dxhi = (__nv_bfloat16*)p;
    cudaGetSymbolAddress(&p, g_xlo);    __nv_bfloat16* dxlo = (__nv_bfloat16*)p;
    cudaGetSymbolAddress(&p, g_zhi);    __nv_bfloat16* dzhi = (__nv_bfloat16*)p;
    cudaGetSymbolAddress(&p, g_zlo);    __nv_bfloat16* dzlo = (__nv_bfloat16*)p;
    cudaGetSymbolAddress(&p, g_raw);    float* draw = (float*)p;
    cudaGetSymbolAddress(&p, g_attn);   float* dattn = (float*)p;
    cudaGetSymbolAddress(&p, g_w1t_hi); __nv_bfloat16* w1h = (__nv_bfloat16*)p;
    cudaGetSymbolAddress(&p, g_w1t_lo); __nv_bfloat16* w1l = (__nv_bfloat16*)p;
    cudaGetSymbolAddress(&p, g_w2t_hi); __nv_bfloat16* w2h = (__nv_bfloat16*)p;
    cudaGetSymbolAddress(&p, g_w2t_lo); __nv_bfloat16* w2l = (__nv_bfloat16*)p;
    cudaGetSymbolAddress(&p, g_wst_hi); __nv_bfloat16* wsh = (__nv_bfloat16*)p;
    cudaGetSymbolAddress(&p, g_wst_lo); __nv_bfloat16* wsl = (__nv_bfloat16*)p;
    cudaGetSymbolAddress(&p, g_bsmall); float* dbs = (float*)p;

    static bool attr_done = false;
    if (!attr_done) {
        cudaFuncSetAttribute(gemm1_glu,
                             cudaFuncAttributeMaxDynamicSharedMemorySize, G1_SMEM_BYTES);
        cudaFuncSetAttribute(gemm_split_mma,
                             cudaFuncAttributeMaxDynamicSharedMemorySize, GSMEM_BYTES);
        cudaFuncSetAttribute(timeconv,
                             cudaFuncAttributeMaxDynamicSharedMemorySize, TC_SMEM);
        attr_done = true;
    }

    // prep: all weight splits in one launch
    prep_all<<<(S_W1 + S_W2 + S_WS + NSP + 255) / 256, 256>>>(
        w1, w2, wf, ww, bf, bw, w1h, w1l, w2h, w2l, wsh, wsl, dbs);

    // 1) x = GLU(query @ w1 + b1), fused
    gemm1_glu<<<dim3(2, BT / BMT), 256, G1_SMEM_BYTES>>>(
        query, w1h, w1l, b1, dx, dxhi, dxlo);
    // 2) raw = x @ [wf|ww] + [bf|bw]
    gemm_split_mma<<<dim3(NSMPAD / BNT, BT / BMT), 256, GSMEM_BYTES>>>(
        dxhi, dxlo, wsh, wsl, dbs, draw, CC, NSP, NSP);
    // 3) channel conv xf + banded softmax
    post_small<<<BT / 8, 256>>>(draw, dx, mask, dattn, dzhi, dzlo);
    // 4) banded attention apply
    timeconv<<<BB * (TT / TCT), 256, TC_SMEM>>>(dx, dattn, mask, dzhi, dzlo);
    // 5) out = z @ w2 + b2
    gemm_split_mma<<<dim3(CC / BNT, BT / BMT), 256, GSMEM_BYTES>>>(
        dzhi, dzlo, w2h, w2l, b2, out, C2, CC, CC);
}